// round 2
// baseline (speedup 1.0000x reference)
#include <cuda_runtime.h>

#define T_SEQ 2048
#define NB 2
#define NH 8
#define NS 32
#define DH 128
#define DMODEL 1024

__device__ float g_Q[NB*NH*T_SEQ*DH];
__device__ float g_K[NB*NH*T_SEQ*DH];
__device__ float g_V[NB*NH*T_SEQ*DH];
__device__ float g_QW[NB*NH*T_SEQ*NS];
__device__ float g_KW[NB*NH*T_SEQ*NS];
__device__ float g_O[NB*T_SEQ*DMODEL];

// FMA-only exp (no MUFU). Exact at x==0, rel err ~1.5e-5.
__device__ __forceinline__ float fast_exp(float x) {
    float t = x * 1.4426950408889634f;
    t = fmaxf(t, -126.0f);
    float fi = floorf(t);
    float f = t - fi;
    float p = 1.5403530e-4f;
    p = fmaf(p, f, 1.3333558e-3f);
    p = fmaf(p, f, 9.6181291e-3f);
    p = fmaf(p, f, 5.5504109e-2f);
    p = fmaf(p, f, 2.4022651e-1f);
    p = fmaf(p, f, 6.9314718e-1f);
    p = fmaf(p, f, 1.0f);
    return p * __int_as_float(((int)fi + 127) << 23);
}

// SGEMM 128x128x16, 256 thr, 8x8/thread.
// MODE 0: x@Wqkv+bqkv -> scatter into g_Q/g_K/g_V [B,H,T,Dh]
// MODE 1: g_O@Wout+bout -> Cout [B*T, D]
template<int MODE>
__global__ void __launch_bounds__(256, 2) sgemm_kernel(
    const float* __restrict__ Ain, const float* __restrict__ Bm,
    const float* __restrict__ bias, float* __restrict__ Cout,
    int N, int K)
{
    __shared__ __align__(16) float As[16][128];
    __shared__ __align__(16) float Bs[16][128];

    const float* A = (MODE == 1) ? (const float*)g_O : Ain;
    int t  = threadIdx.x;
    int tx = t & 15, ty = t >> 4;
    int n0 = blockIdx.x * 128, m0 = blockIdx.y * 128;

    int arow = t >> 1, acol = (t & 1) * 8;
    int brow = t >> 4, bcol = (t & 15) * 8;

    const float* Ap = A  + (size_t)(m0 + arow) * K + acol;
    const float* Bp = Bm + (size_t)brow * N + n0 + bcol;

    float acc[8][8];
    #pragma unroll
    for (int i = 0; i < 8; i++)
        #pragma unroll
        for (int j = 0; j < 8; j++) acc[i][j] = 0.0f;

    for (int kt = 0; kt < K / 16; kt++) {
        float4 a0 = *(const float4*)(Ap);
        float4 a1 = *(const float4*)(Ap + 4);
        float4 b0 = *(const float4*)(Bp);
        float4 b1 = *(const float4*)(Bp + 4);
        __syncthreads();
        As[acol+0][arow] = a0.x; As[acol+1][arow] = a0.y;
        As[acol+2][arow] = a0.z; As[acol+3][arow] = a0.w;
        As[acol+4][arow] = a1.x; As[acol+5][arow] = a1.y;
        As[acol+6][arow] = a1.z; As[acol+7][arow] = a1.w;
        *(float4*)&Bs[brow][bcol]   = b0;
        *(float4*)&Bs[brow][bcol+4] = b1;
        __syncthreads();
        #pragma unroll
        for (int kk = 0; kk < 16; kk++) {
            float4 t0 = *(const float4*)&As[kk][ty*4];
            float4 t1 = *(const float4*)&As[kk][64 + ty*4];
            float4 t2 = *(const float4*)&Bs[kk][tx*4];
            float4 t3 = *(const float4*)&Bs[kk][64 + tx*4];
            float ar[8] = {t0.x,t0.y,t0.z,t0.w,t1.x,t1.y,t1.z,t1.w};
            float br[8] = {t2.x,t2.y,t2.z,t2.w,t3.x,t3.y,t3.z,t3.w};
            #pragma unroll
            for (int i = 0; i < 8; i++)
                #pragma unroll
                for (int j = 0; j < 8; j++)
                    acc[i][j] = fmaf(ar[i], br[j], acc[i][j]);
        }
        Ap += 16;
        Bp += (size_t)16 * N;
    }

    float4 bi0 = *(const float4*)&bias[n0 + tx*4];
    float4 bi1 = *(const float4*)&bias[n0 + 64 + tx*4];
    float bv[8] = {bi0.x,bi0.y,bi0.z,bi0.w,bi1.x,bi1.y,bi1.z,bi1.w};

    #pragma unroll
    for (int i = 0; i < 8; i++) {
        int m = m0 + ((i < 4) ? (ty*4 + i) : (64 + ty*4 + i - 4));
        float4 lo = make_float4(acc[i][0]+bv[0], acc[i][1]+bv[1], acc[i][2]+bv[2], acc[i][3]+bv[3]);
        float4 hi = make_float4(acc[i][4]+bv[4], acc[i][5]+bv[5], acc[i][6]+bv[6], acc[i][7]+bv[7]);
        if (MODE == 0) {
            int g = n0 >> 7;           // 0..23: part*8 + h
            int part = g >> 3, h = g & 7;
            float* dst = (part == 0) ? g_Q : ((part == 1) ? g_K : g_V);
            int bb = m >> 11, tt = m & 2047;
            size_t base = ((size_t)(bb * NH + h) * T_SEQ + tt) * DH;
            *(float4*)&dst[base + tx*4]      = lo;
            *(float4*)&dst[base + 64 + tx*4] = hi;
        } else {
            size_t base = (size_t)m * N;
            *(float4*)&Cout[base + n0 + tx*4]      = lo;
            *(float4*)&Cout[base + n0 + 64 + tx*4] = hi;
        }
    }
}

// splat weights: exp(-0.5*(d/(scale+eps))^2) * (isK ? 1 : amp)
// block = 8 rows (one (b,h) slice); warp w = row, lane = splat s.
__global__ void __launch_bounds__(256) weights_kernel(
    const float* __restrict__ centers, const float* __restrict__ lsc,
    const float* __restrict__ lam)
{
    __shared__ float c_sm[32][129];
    __shared__ float q_sm[8][128];

    int isK = blockIdx.y;
    int r0  = blockIdx.x * 8;
    int t = threadIdx.x, w = t >> 5, lane = t & 31;
    int h = (r0 >> 11) & 7;

    const float* cp = centers + h * NS * DH;
    for (int u = t; u < NS * DH; u += 256)
        c_sm[u >> 7][u & 127] = cp[u];

    const float* src = (isK ? g_K : g_Q) + (size_t)r0 * DH;
    #pragma unroll
    for (int u = 0; u < 4; u++)
        q_sm[w][lane + 32*u] = src[w * DH + lane + 32*u];
    __syncthreads();

    int s = lane;
    float scale = fast_exp(lsc[h * NS + s]);
    float inv = 1.0f / (scale + 1e-6f);
    float amp = isK ? 1.0f : fast_exp(lam[h * NS + s]);
    float coef = -0.5f * inv * inv;

    float d2 = 0.0f;
    #pragma unroll
    for (int k = 0; k < 128; k++) {
        float diff = q_sm[w][k] - c_sm[s][k];
        d2 = fmaf(diff, diff, d2);
    }
    (isK ? g_KW : g_QW)[(size_t)(r0 + w) * NS + s] = fast_exp(d2 * coef) * amp;
}

// fused logits + softmax + attention write + AV
// block = (b, 16 i-rows), warp w = head h, all j tiles of 32.
__global__ void __launch_bounds__(256, 2) attn_kernel(
    const float* __restrict__ temp, float* __restrict__ attn)
{
    __shared__ __align__(16) float qa_sm[NH][16][NS];
    __shared__ float p_sm[16][288];   // [i][j*9+h] conflict-free
    __shared__ float m_sm[NH][16];
    __shared__ float li_sm[NH][16];

    int b = blockIdx.y, i0 = blockIdx.x * 16;
    int t = threadIdx.x, w = t >> 5, lane = t & 31;
    float invT = 1.0f / temp[0];

    for (int u = t; u < NH * 16 * NS; u += 256) {
        int h = u >> 9, i = (u >> 5) & 15, s = u & 31;
        qa_sm[h][i][s] = g_QW[((size_t)(b * NH + h) * T_SEQ + i0 + i) * NS + s];
    }
    __syncthreads();

    const float* KWh = g_KW + (size_t)(b * NH + w) * T_SEQ * NS;

    // phase 1: lane-local online max/sum over its j-subset
    float mloc[16], sloc[16];
    #pragma unroll
    for (int i = 0; i < 16; i++) { mloc[i] = -1e30f; sloc[i] = 0.0f; }

    for (int j0 = 0; j0 < T_SEQ; j0 += 32) {
        float4 kw[8];
        const float4* kp = (const float4*)(KWh + (size_t)(j0 + lane) * NS);
        #pragma unroll
        for (int q = 0; q < 8; q++) kw[q] = kp[q];
        #pragma unroll
        for (int i = 0; i < 16; i++) {
            const float4* qp = (const float4*)qa_sm[w][i];
            float acc = 0.0f;
            #pragma unroll
            for (int q = 0; q < 8; q++) {
                float4 a4 = qp[q];
                acc = fmaf(a4.x, kw[q].x, acc);
                acc = fmaf(a4.y, kw[q].y, acc);
                acc = fmaf(a4.z, kw[q].z, acc);
                acc = fmaf(a4.w, kw[q].w, acc);
            }
            float l = acc * invT;
            float nm = fmaxf(mloc[i], l);
            sloc[i] = fmaf(sloc[i], fast_exp(mloc[i] - nm), fast_exp(l - nm));
            mloc[i] = nm;
        }
    }
    #pragma unroll
    for (int i = 0; i < 16; i++) {
        float m = mloc[i], sv = sloc[i];
        #pragma unroll
        for (int off = 16; off > 0; off >>= 1) {
            float mo = __shfl_xor_sync(0xffffffffu, m, off);
            float so = __shfl_xor_sync(0xffffffffu, sv, off);
            float nm = fmaxf(m, mo);
            sv = sv * fast_exp(m - nm) + so * fast_exp(mo - nm);
            m = nm;
        }
        if (lane == 0) { m_sm[w][i] = m; li_sm[w][i] = 1.0f / sv; }
    }
    __syncthreads();

    // phase 2: recompute + write attention + accumulate O
    float o[16][4];
    #pragma unroll
    for (int i = 0; i < 16; i++) { o[i][0]=o[i][1]=o[i][2]=o[i][3]=0.0f; }

    const float* Vh = g_V + (size_t)(b * NH + w) * T_SEQ * DH;
    int d4 = lane * 4;
    int jj_w = t >> 3, hh_w = t & 7;

    for (int j0 = 0; j0 < T_SEQ; j0 += 32) {
        {
            float4 kw[8];
            const float4* kp = (const float4*)(KWh + (size_t)(j0 + lane) * NS);
            #pragma unroll
            for (int q = 0; q < 8; q++) kw[q] = kp[q];
            #pragma unroll
            for (int i = 0; i < 16; i++) {
                const float4* qp = (const float4*)qa_sm[w][i];
                float acc = 0.0f;
                #pragma unroll
                for (int q = 0; q < 8; q++) {
                    float4 a4 = qp[q];
                    acc = fmaf(a4.x, kw[q].x, acc);
                    acc = fmaf(a4.y, kw[q].y, acc);
                    acc = fmaf(a4.z, kw[q].z, acc);
                    acc = fmaf(a4.w, kw[q].w, acc);
                }
                float l = acc * invT;
                p_sm[i][lane * 9 + w] = fast_exp(l - m_sm[w][i]) * li_sm[w][i];
            }
        }
        __syncthreads();

        #pragma unroll
        for (int i = 0; i < 16; i++) {
            attn[(((size_t)(b * T_SEQ + i0 + i)) * T_SEQ + j0 + jj_w) * NH + hh_w] =
                p_sm[i][jj_w * 9 + hh_w];
        }

        #pragma unroll 4
        for (int jj = 0; jj < 32; jj++) {
            float4 v4 = *(const float4*)(Vh + (size_t)(j0 + jj) * DH + d4);
            #pragma unroll
            for (int i = 0; i < 16; i++) {
                float a = p_sm[i][jj * 9 + w];
                o[i][0] = fmaf(a, v4.x, o[i][0]);
                o[i][1] = fmaf(a, v4.y, o[i][1]);
                o[i][2] = fmaf(a, v4.z, o[i][2]);
                o[i][3] = fmaf(a, v4.w, o[i][3]);
            }
        }
        __syncthreads();
    }

    #pragma unroll
    for (int i = 0; i < 16; i++) {
        *(float4*)&g_O[(size_t)(b * T_SEQ + i0 + i) * DMODEL + w * DH + d4] =
            make_float4(o[i][0], o[i][1], o[i][2], o[i][3]);
    }
}

extern "C" void kernel_launch(void* const* d_in, const int* in_sizes, int n_in,
                              void* d_out, int out_size)
{
    const float* x       = (const float*)d_in[0];
    const float* Wqkv    = (const float*)d_in[1];
    const float* bqkv    = (const float*)d_in[2];
    const float* Wout    = (const float*)d_in[3];
    const float* bout    = (const float*)d_in[4];
    const float* centers = (const float*)d_in[5];
    const float* lsc     = (const float*)d_in[6];
    const float* lam     = (const float*)d_in[7];
    const float* temp    = (const float*)d_in[8];

    float* out  = (float*)d_out;
    float* attn = out + (size_t)NB * T_SEQ * DMODEL;

    sgemm_kernel<0><<<dim3(3 * DMODEL / 128, (NB * T_SEQ) / 128), 256>>>(
        x, Wqkv, bqkv, nullptr, 3 * DMODEL, DMODEL);

    weights_kernel<<<dim3((NB * NH * T_SEQ) / 8, 2), 256>>>(centers, lsc, lam);

    attn_kernel<<<dim3(T_SEQ / 16, NB), 256>>>(temp, attn);

    sgemm_kernel<1><<<dim3(DMODEL / 128, (NB * T_SEQ) / 128), 256>>>(
        nullptr, Wout, bout, out, DMODEL, DMODEL);
}

// round 3
// speedup vs baseline: 1.1553x; 1.1553x over previous
#include <cuda_runtime.h>

#define T_SEQ 2048
#define NB 2
#define NH 8
#define NS 32
#define DH 128
#define DMODEL 1024

__device__ float g_Q[NB*NH*T_SEQ*DH];
__device__ float g_K[NB*NH*T_SEQ*DH];
__device__ float g_V[NB*NH*T_SEQ*DH];
__device__ float g_QW[NB*NH*T_SEQ*NS];
__device__ float g_KW[NB*NH*T_SEQ*NS];
__device__ float g_O[NB*T_SEQ*DMODEL];
__device__ float g_P[(size_t)NB*NH*T_SEQ*T_SEQ];   // unnormalized exp(logits), bhij
__device__ float g_Sinv[NB*NH*T_SEQ];

// FMA-only exp (no MUFU). Exact at x==0, rel err ~1.5e-5.
__device__ __forceinline__ float fast_exp(float x) {
    float t = x * 1.4426950408889634f;
    t = fmaxf(t, -126.0f);
    float fi = floorf(t);
    float f = t - fi;
    float p = 1.5403530e-4f;
    p = fmaf(p, f, 1.3333558e-3f);
    p = fmaf(p, f, 9.6181291e-3f);
    p = fmaf(p, f, 5.5504109e-2f);
    p = fmaf(p, f, 2.4022651e-1f);
    p = fmaf(p, f, 6.9314718e-1f);
    p = fmaf(p, f, 1.0f);
    return p * __int_as_float(((int)fi + 127) << 23);
}

// SGEMM 128x128x16, 256 thr, 8x8/thread.
// MODE 0: x@Wqkv+bqkv -> scatter into g_Q/g_K/g_V [B,H,T,Dh]
// MODE 1: g_O@Wout+bout -> Cout [B*T, D]
template<int MODE>
__global__ void __launch_bounds__(256, 2) sgemm_kernel(
    const float* __restrict__ Ain, const float* __restrict__ Bm,
    const float* __restrict__ bias, float* __restrict__ Cout,
    int N, int K)
{
    __shared__ __align__(16) float As[16][128];
    __shared__ __align__(16) float Bs[16][128];

    const float* A = (MODE == 1) ? (const float*)g_O : Ain;
    int t  = threadIdx.x;
    int tx = t & 15, ty = t >> 4;
    int n0 = blockIdx.x * 128, m0 = blockIdx.y * 128;

    int arow = t >> 1, acol = (t & 1) * 8;
    int brow = t >> 4, bcol = (t & 15) * 8;

    const float* Ap = A  + (size_t)(m0 + arow) * K + acol;
    const float* Bp = Bm + (size_t)brow * N + n0 + bcol;

    float acc[8][8];
    #pragma unroll
    for (int i = 0; i < 8; i++)
        #pragma unroll
        for (int j = 0; j < 8; j++) acc[i][j] = 0.0f;

    for (int kt = 0; kt < K / 16; kt++) {
        float4 a0 = *(const float4*)(Ap);
        float4 a1 = *(const float4*)(Ap + 4);
        float4 b0 = *(const float4*)(Bp);
        float4 b1 = *(const float4*)(Bp + 4);
        __syncthreads();
        As[acol+0][arow] = a0.x; As[acol+1][arow] = a0.y;
        As[acol+2][arow] = a0.z; As[acol+3][arow] = a0.w;
        As[acol+4][arow] = a1.x; As[acol+5][arow] = a1.y;
        As[acol+6][arow] = a1.z; As[acol+7][arow] = a1.w;
        *(float4*)&Bs[brow][bcol]   = b0;
        *(float4*)&Bs[brow][bcol+4] = b1;
        __syncthreads();
        #pragma unroll
        for (int kk = 0; kk < 16; kk++) {
            float4 t0 = *(const float4*)&As[kk][ty*4];
            float4 t1 = *(const float4*)&As[kk][64 + ty*4];
            float4 t2 = *(const float4*)&Bs[kk][tx*4];
            float4 t3 = *(const float4*)&Bs[kk][64 + tx*4];
            float ar[8] = {t0.x,t0.y,t0.z,t0.w,t1.x,t1.y,t1.z,t1.w};
            float br[8] = {t2.x,t2.y,t2.z,t2.w,t3.x,t3.y,t3.z,t3.w};
            #pragma unroll
            for (int i = 0; i < 8; i++)
                #pragma unroll
                for (int j = 0; j < 8; j++)
                    acc[i][j] = fmaf(ar[i], br[j], acc[i][j]);
        }
        Ap += 16;
        Bp += (size_t)16 * N;
    }

    float4 bi0 = *(const float4*)&bias[n0 + tx*4];
    float4 bi1 = *(const float4*)&bias[n0 + 64 + tx*4];
    float bv[8] = {bi0.x,bi0.y,bi0.z,bi0.w,bi1.x,bi1.y,bi1.z,bi1.w};

    #pragma unroll
    for (int i = 0; i < 8; i++) {
        int m = m0 + ((i < 4) ? (ty*4 + i) : (64 + ty*4 + i - 4));
        float4 lo = make_float4(acc[i][0]+bv[0], acc[i][1]+bv[1], acc[i][2]+bv[2], acc[i][3]+bv[3]);
        float4 hi = make_float4(acc[i][4]+bv[4], acc[i][5]+bv[5], acc[i][6]+bv[6], acc[i][7]+bv[7]);
        if (MODE == 0) {
            int g = n0 >> 7;
            int part = g >> 3, h = g & 7;
            float* dst = (part == 0) ? g_Q : ((part == 1) ? g_K : g_V);
            int bb = m >> 11, tt = m & 2047;
            size_t base = ((size_t)(bb * NH + h) * T_SEQ + tt) * DH;
            *(float4*)&dst[base + tx*4]      = lo;
            *(float4*)&dst[base + 64 + tx*4] = hi;
        } else {
            size_t base = (size_t)m * N;
            *(float4*)&Cout[base + n0 + tx*4]      = lo;
            *(float4*)&Cout[base + n0 + 64 + tx*4] = hi;
        }
    }
}

// splat weights: exp(-0.5*(d/(scale+eps))^2) * (isK ? 1 : amp)
__global__ void __launch_bounds__(256) weights_kernel(
    const float* __restrict__ centers, const float* __restrict__ lsc,
    const float* __restrict__ lam)
{
    __shared__ float c_sm[32][129];
    __shared__ float q_sm[8][128];

    int isK = blockIdx.y;
    int r0  = blockIdx.x * 8;
    int t = threadIdx.x, w = t >> 5, lane = t & 31;
    int h = (r0 >> 11) & 7;

    const float* cp = centers + h * NS * DH;
    for (int u = t; u < NS * DH; u += 256)
        c_sm[u >> 7][u & 127] = cp[u];

    const float* src = (isK ? g_K : g_Q) + (size_t)r0 * DH;
    #pragma unroll
    for (int u = 0; u < 4; u++)
        q_sm[w][lane + 32*u] = src[w * DH + lane + 32*u];
    __syncthreads();

    int s = lane;
    float scale = fast_exp(lsc[h * NS + s]);
    float inv = 1.0f / (scale + 1e-6f);
    float amp = isK ? 1.0f : fast_exp(lam[h * NS + s]);
    float coef = -0.5f * inv * inv;

    float d2 = 0.0f;
    #pragma unroll
    for (int k = 0; k < 128; k++) {
        float diff = q_sm[w][k] - c_sm[s][k];
        d2 = fmaf(diff, diff, d2);
    }
    (isK ? g_KW : g_QW)[(size_t)(r0 + w) * NS + s] = fast_exp(d2 * coef) * amp;
}

// logits + exp + row-sum. Block = (b,h, 128 i-rows). Warp w -> 16 i rows.
// Writes UNNORMALIZED e to g_P[bh][i][j] (coalesced), 1/sum to g_Sinv.
// No max pass needed: logits in [0, NS/temp], exp cannot overflow fp32.
__global__ void __launch_bounds__(256) logits_kernel(const float* __restrict__ temp)
{
    __shared__ __align__(16) float qa_sm[128][NS];

    int bh = blockIdx.y;
    int i0 = blockIdx.x * 128;
    int t = threadIdx.x, w = t >> 5, lane = t & 31;
    float invT = 1.0f / temp[0];

    const float* QWp = g_QW + ((size_t)bh * T_SEQ + i0) * NS;
    for (int u = t; u < 128 * NS; u += 256)
        qa_sm[u >> 5][u & 31] = QWp[u];
    __syncthreads();

    const float* KWh = g_KW + (size_t)bh * T_SEQ * NS;
    float* Pw = g_P + ((size_t)bh * T_SEQ + i0 + w * 16) * T_SEQ;

    float sloc[16];
    #pragma unroll
    for (int i = 0; i < 16; i++) sloc[i] = 0.0f;

    for (int j0 = 0; j0 < T_SEQ; j0 += 32) {
        float4 kw[8];
        const float4* kp = (const float4*)(KWh + (size_t)(j0 + lane) * NS);
        #pragma unroll
        for (int q = 0; q < 8; q++) kw[q] = kp[q];
        #pragma unroll
        for (int i = 0; i < 16; i++) {
            const float4* qp = (const float4*)qa_sm[w * 16 + i];
            float acc = 0.0f;
            #pragma unroll
            for (int q = 0; q < 8; q++) {
                float4 a4 = qp[q];
                acc = fmaf(a4.x, kw[q].x, acc);
                acc = fmaf(a4.y, kw[q].y, acc);
                acc = fmaf(a4.z, kw[q].z, acc);
                acc = fmaf(a4.w, kw[q].w, acc);
            }
            float e = fast_exp(acc * invT);
            sloc[i] += e;
            Pw[(size_t)i * T_SEQ + j0 + lane] = e;
        }
    }

    #pragma unroll
    for (int i = 0; i < 16; i++) {
        float sv = sloc[i];
        #pragma unroll
        for (int off = 16; off > 0; off >>= 1)
            sv += __shfl_xor_sync(0xffffffffu, sv, off);
        if (lane == 0)
            g_Sinv[(size_t)bh * T_SEQ + i0 + w * 16 + i] = 1.0f / sv;
    }
}

// AV = (g_P @ V) * inv_s. Batched 128x128xK GEMM per (b,h). N = DH = 128.
__global__ void __launch_bounds__(256, 2) av_gemm_kernel()
{
    __shared__ __align__(16) float As[16][128];
    __shared__ __align__(16) float Bs[16][128];

    int bh = blockIdx.y;
    int m0 = blockIdx.x * 128;
    int t  = threadIdx.x;
    int tx = t & 15, ty = t >> 4;

    const float* A = g_P + (size_t)bh * T_SEQ * T_SEQ;
    const float* B = g_V + (size_t)bh * T_SEQ * DH;

    int arow = t >> 1, acol = (t & 1) * 8;
    int brow = t >> 4, bcol = (t & 15) * 8;

    const float* Ap = A + (size_t)(m0 + arow) * T_SEQ + acol;
    const float* Bp = B + (size_t)brow * DH + bcol;

    float acc[8][8];
    #pragma unroll
    for (int i = 0; i < 8; i++)
        #pragma unroll
        for (int j = 0; j < 8; j++) acc[i][j] = 0.0f;

    for (int kt = 0; kt < T_SEQ / 16; kt++) {
        float4 a0 = *(const float4*)(Ap);
        float4 a1 = *(const float4*)(Ap + 4);
        float4 b0 = *(const float4*)(Bp);
        float4 b1 = *(const float4*)(Bp + 4);
        __syncthreads();
        As[acol+0][arow] = a0.x; As[acol+1][arow] = a0.y;
        As[acol+2][arow] = a0.z; As[acol+3][arow] = a0.w;
        As[acol+4][arow] = a1.x; As[acol+5][arow] = a1.y;
        As[acol+6][arow] = a1.z; As[acol+7][arow] = a1.w;
        *(float4*)&Bs[brow][bcol]   = b0;
        *(float4*)&Bs[brow][bcol+4] = b1;
        __syncthreads();
        #pragma unroll
        for (int kk = 0; kk < 16; kk++) {
            float4 t0 = *(const float4*)&As[kk][ty*4];
            float4 t1 = *(const float4*)&As[kk][64 + ty*4];
            float4 t2 = *(const float4*)&Bs[kk][tx*4];
            float4 t3 = *(const float4*)&Bs[kk][64 + tx*4];
            float ar[8] = {t0.x,t0.y,t0.z,t0.w,t1.x,t1.y,t1.z,t1.w};
            float br[8] = {t2.x,t2.y,t2.z,t2.w,t3.x,t3.y,t3.z,t3.w};
            #pragma unroll
            for (int i = 0; i < 8; i++)
                #pragma unroll
                for (int j = 0; j < 8; j++)
                    acc[i][j] = fmaf(ar[i], br[j], acc[i][j]);
        }
        Ap += 16;
        Bp += (size_t)16 * DH;
    }

    int b = bh >> 3, h = bh & 7;
    #pragma unroll
    for (int i = 0; i < 8; i++) {
        int m = m0 + ((i < 4) ? (ty*4 + i) : (64 + ty*4 + i - 4));
        float inv = g_Sinv[(size_t)bh * T_SEQ + m];
        size_t base = (size_t)(b * T_SEQ + m) * DMODEL + h * DH;
        *(float4*)&g_O[base + tx*4] = make_float4(acc[i][0]*inv, acc[i][1]*inv,
                                                  acc[i][2]*inv, acc[i][3]*inv);
        *(float4*)&g_O[base + 64 + tx*4] = make_float4(acc[i][4]*inv, acc[i][5]*inv,
                                                       acc[i][6]*inv, acc[i][7]*inv);
    }
}

// bhij -> bijh transpose + normalize. Block = (b,i). Warp w = head h.
__global__ void __launch_bounds__(256) transpose_kernel(float* __restrict__ attn)
{
    __shared__ float p_sm[512 * 9];

    int bi = blockIdx.x;
    int b = bi >> 11, i = bi & 2047;
    int t = threadIdx.x, w = t >> 5, lane = t & 31;

    const float* src = g_P + ((size_t)(b * NH + w) * T_SEQ + i) * T_SEQ;
    float inv = g_Sinv[(size_t)(b * NH + w) * T_SEQ + i];
    float* dst = attn + ((size_t)(b * T_SEQ + i)) * T_SEQ * NH;

    for (int c = 0; c < 4; c++) {
        #pragma unroll
        for (int r = 0; r < 16; r++) {
            int j = r * 32 + lane;
            p_sm[j * 9 + w] = src[c * 512 + j] * inv;
        }
        __syncthreads();
        #pragma unroll
        for (int r = 0; r < 16; r++) {
            int u = r * 256 + t;
            dst[c * 4096 + u] = p_sm[(u >> 3) * 9 + (u & 7)];
        }
        __syncthreads();
    }
}

extern "C" void kernel_launch(void* const* d_in, const int* in_sizes, int n_in,
                              void* d_out, int out_size)
{
    const float* x       = (const float*)d_in[0];
    const float* Wqkv    = (const float*)d_in[1];
    const float* bqkv    = (const float*)d_in[2];
    const float* Wout    = (const float*)d_in[3];
    const float* bout    = (const float*)d_in[4];
    const float* centers = (const float*)d_in[5];
    const float* lsc     = (const float*)d_in[6];
    const float* lam     = (const float*)d_in[7];
    const float* temp    = (const float*)d_in[8];

    float* out  = (float*)d_out;
    float* attn = out + (size_t)NB * T_SEQ * DMODEL;

    sgemm_kernel<0><<<dim3(3 * DMODEL / 128, (NB * T_SEQ) / 128), 256>>>(
        x, Wqkv, bqkv, nullptr, 3 * DMODEL, DMODEL);

    weights_kernel<<<dim3((NB * NH * T_SEQ) / 8, 2), 256>>>(centers, lsc, lam);

    logits_kernel<<<dim3(T_SEQ / 128, NB * NH), 256>>>(temp);

    av_gemm_kernel<<<dim3(T_SEQ / 128, NB * NH), 256>>>();

    transpose_kernel<<<NB * T_SEQ, 256>>>(attn);

    sgemm_kernel<1><<<dim3(DMODEL / 128, (NB * T_SEQ) / 128), 256>>>(
        nullptr, Wout, bout, out, DMODEL, DMODEL);
}